// round 6
// baseline (speedup 1.0000x reference)
#include <cuda_runtime.h>
#include <cuda_bf16.h>
#include <cstdint>

#define SEQ   4096
#define BATCH 4
#define DIM   512
#define M0    (BATCH * SEQ)

// ---------------------------------------------------------------------------
// Device scratch (allocation-free rule: __device__ globals)
// ---------------------------------------------------------------------------
__device__ __nv_bfloat16 g_XH[(size_t)M0 * DIM];
__device__ __nv_bfloat16 g_XL[(size_t)M0 * DIM];
__device__ __nv_bfloat16 g_WtH[4 * DIM * DIM];   // Wq^T,Wk^T,Wv^T,Wo^T (hi)
__device__ __nv_bfloat16 g_WtL[4 * DIM * DIM];   // (lo)
__device__ __nv_bfloat16 g_QH[(size_t)M0 * DIM];
__device__ __nv_bfloat16 g_QL[(size_t)M0 * DIM];
__device__ __nv_bfloat16 g_KH[(size_t)M0 * DIM];
__device__ __nv_bfloat16 g_KL[(size_t)M0 * DIM];
__device__ __nv_bfloat16 g_VtH[(size_t)BATCH * DIM * SEQ];  // [b][h][s]
__device__ __nv_bfloat16 g_VtL[(size_t)BATCH * DIM * SEQ];
__device__ __nv_bfloat16 g_PH[(size_t)BATCH * SEQ * SEQ];   // unnormalized exp(S)
__device__ __nv_bfloat16 g_PL[(size_t)BATCH * SEQ * SEQ];
__device__ float         g_rowpart[(size_t)M0 * 64];        // per-row partial sums
__device__ float         g_rsinv[M0];                       // 1/rowsum
__device__ __nv_bfloat16 g_YH[(size_t)M0 * DIM];
__device__ __nv_bfloat16 g_YL[(size_t)M0 * DIM];

// ---------------------------------------------------------------------------
// PTX helpers (sm_103 baseline only: ldmatrix + mma.sync + cp.async)
// ---------------------------------------------------------------------------
__device__ __forceinline__ uint32_t smem_to_u32(const void* p) {
    uint32_t a;
    asm("{ .reg .u64 t; cvta.to.shared.u64 t, %1; cvt.u32.u64 %0, t; }"
        : "=r"(a) : "l"(p));
    return a;
}

__device__ __forceinline__ void cp16(uint32_t s, const void* g) {
    asm volatile("cp.async.cg.shared.global [%0], [%1], 16;" :: "r"(s), "l"(g));
}
#define CP_COMMIT() asm volatile("cp.async.commit_group;" ::: "memory")
#define CP_WAIT(n)  asm volatile("cp.async.wait_group %0;" :: "n"(n) : "memory")

#define LDM4(r0, r1, r2, r3, addr) \
    asm volatile("ldmatrix.sync.aligned.m8n8.x4.shared.b16 {%0,%1,%2,%3}, [%4];" \
                 : "=r"(r0), "=r"(r1), "=r"(r2), "=r"(r3) : "r"(addr))

__device__ __forceinline__ void mma16816(float* c, const uint32_t* a,
                                         const uint32_t* b) {
    asm volatile(
        "mma.sync.aligned.m16n8k16.row.col.f32.bf16.bf16.f32 "
        "{%0,%1,%2,%3}, {%4,%5,%6,%7}, {%8,%9}, {%0,%1,%2,%3};"
        : "+f"(c[0]), "+f"(c[1]), "+f"(c[2]), "+f"(c[3])
        : "r"(a[0]), "r"(a[1]), "r"(a[2]), "r"(a[3]), "r"(b[0]), "r"(b[1]));
}

__device__ __forceinline__ void split2(float v, __nv_bfloat16& h, __nv_bfloat16& l) {
    h = __float2bfloat16(v);
    l = __float2bfloat16(v - __bfloat162float(h));
}

__device__ __forceinline__ uint32_t pack2(__nv_bfloat16 a, __nv_bfloat16 b) {
    __nv_bfloat162 t = __halves2bfloat162(a, b);
    return *(uint32_t*)&t;
}

// 64B-row XOR swizzle: 16B chunk position = c16 ^ ((row>>1)&3).
// Conflict-free for 8-consecutive-row ldmatrix groups and cp.async stores.
__device__ __forceinline__ uint32_t swz(uint32_t r, uint32_t c16) {
    return r * 64u + ((c16 ^ ((r >> 1) & 3u)) << 4);
}

// ---------------------------------------------------------------------------
// Prep kernels
// ---------------------------------------------------------------------------
__global__ void k_prep_x(const float* __restrict__ x) {
    size_t i = (size_t)blockIdx.x * 256 + threadIdx.x;
    if (i < (size_t)M0 * DIM) split2(x[i], g_XH[i], g_XL[i]);
}

__global__ void k_prep_w(const float* __restrict__ Wq, const float* __restrict__ Wk,
                         const float* __restrict__ Wv, const float* __restrict__ Wo) {
    int i = blockIdx.x * 256 + threadIdx.x;
    if (i >= 4 * DIM * DIM) return;
    int w = i >> 18, r = (i >> 9) & 511, c = i & 511;
    const float* src = (w == 0) ? Wq : (w == 1) ? Wk : (w == 2) ? Wv : Wo;
    split2(src[c * DIM + r], g_WtH[i], g_WtL[i]);   // Wt[r=out][c=in] = W[c][r]
}

// Reduce 64 partials per row -> 1/rowsum
__global__ void k_rowsum() {
    int r = blockIdx.x * 256 + threadIdx.x;
    if (r >= M0) return;
    const float4* p = (const float4*)(g_rowpart + (size_t)r * 64);
    float s = 0.f;
    #pragma unroll
    for (int i = 0; i < 16; i++) {
        float4 v = p[i];
        s += (v.x + v.y) + (v.z + v.w);
    }
    g_rsinv[r] = 1.f / s;
}

// ---------------------------------------------------------------------------
// Split-bf16 GEMM via mma.sync: D[m][n] = sum_k A[m][k] * B[n][k]
// Tile 128x128, BK=32, 3-stage cp.async pipeline (one barrier per stage),
// 8 warps = 4(M) x 2(N), each warp 32x64 in registers. 2 CTAs/SM.
// cfg 0: QKV   epi: +bias, split (V transposed)
// cfg 1: score epi: exp(s), split -> P, per-row partial sums (fused softmax)
// cfg 2: PV    epi: * 1/rowsum, split -> Y
// cfg 3: out   epi: +bias, fp32 -> d_out
// ---------------------------------------------------------------------------
#define TILEB  8192                   // 128 rows x 64B (swizzled)
#define STAGEB (4 * TILEB)            // 32768
#define NSTAGE 3
#define SMEMB  (NSTAGE * STAGEB)      // 98304

__global__ void __launch_bounds__(256, 2)
k_gemm(int cfg, const float* __restrict__ b0, const float* __restrict__ b1,
       const float* __restrict__ b2, float* __restrict__ outp) {
    extern __shared__ char smem[];
    const int tid = threadIdx.x, wid = tid >> 5, lid = tid & 31;
    const int wm = wid & 3, wn = wid >> 2;           // warp grid 4(M) x 2(N)
    const int nt = blockIdx.x, mt = blockIdx.y, bz = blockIdx.z;

    const __nv_bfloat16 *AH, *AL, *BH, *BL;
    int lda, ldb, K;
    if (cfg == 0) {
        AH = g_XH; AL = g_XL; BH = g_WtH; BL = g_WtL;
        lda = DIM; ldb = DIM; K = DIM;
    } else if (cfg == 1) {
        size_t ao = (size_t)bz * SEQ * DIM;
        AH = g_QH + ao; AL = g_QL + ao; BH = g_KH + ao; BL = g_KL + ao;
        lda = DIM; ldb = DIM; K = DIM;
    } else if (cfg == 2) {
        size_t ao = (size_t)bz * SEQ * SEQ, vo = (size_t)bz * DIM * SEQ;
        AH = g_PH + ao; AL = g_PL + ao; BH = g_VtH + vo; BL = g_VtL + vo;
        lda = SEQ; ldb = SEQ; K = SEQ;
    } else {
        AH = g_YH; AL = g_YL;
        BH = g_WtH + 3 * DIM * DIM; BL = g_WtL + 3 * DIM * DIM;
        lda = DIM; ldb = DIM; K = DIM;
    }

    const int m0 = mt * 128, n0 = nt * 128;
    const uint32_t sb = smem_to_u32(smem);

    const __nv_bfloat16* tp[4];
    tp[0] = AH + (size_t)m0 * lda;
    tp[1] = AL + (size_t)m0 * lda;
    tp[2] = BH + (size_t)n0 * ldb;
    tp[3] = BL + (size_t)n0 * ldb;

    float acc[2][8][4];
    #pragma unroll
    for (int i = 0; i < 2; i++)
        #pragma unroll
        for (int j = 0; j < 8; j++)
            #pragma unroll
            for (int e = 0; e < 4; e++) acc[i][j][e] = 0.f;

    const int nst = K >> 5;

    auto load_stage = [&](int s) {
        const uint32_t base = sb + (uint32_t)(s % NSTAGE) * STAGEB;
        const int k0 = s << 5;
        #pragma unroll
        for (int t = tid; t < 2048; t += 256) {
            const int tl = t >> 9;            // tile 0..3
            const int idx = t & 511;          // 128 rows x 4 chunks
            const int r = idx >> 2, c = idx & 3;
            const int ld = (tl < 2) ? lda : ldb;
            cp16(base + (uint32_t)tl * TILEB + swz((uint32_t)r, (uint32_t)c),
                 tp[tl] + (size_t)r * ld + (k0 + c * 8));
        }
        CP_COMMIT();
    };

    load_stage(0);
    load_stage(1);

    for (int s = 0; s < nst; s++) {
        if (s == nst - 1) { CP_WAIT(0); } else { CP_WAIT(1); }
        __syncthreads();                       // stage-s visible + WAR for s+2
        if (s + 2 < nst) load_stage(s + 2);

        const uint32_t sbase = sb + (uint32_t)(s % NSTAGE) * STAGEB;
        const uint32_t aHb = sbase, aLb = sbase + TILEB;
        const uint32_t bHb = sbase + 2 * TILEB, bLb = sbase + 3 * TILEB;

        #pragma unroll
        for (int ks = 0; ks < 2; ks++) {
            uint32_t ah[2][4], al[2][4];
            #pragma unroll
            for (int i = 0; i < 2; i++) {
                const uint32_t r = (uint32_t)(wm * 32 + i * 16 + (lid & 15));
                const uint32_t c16 = (uint32_t)(ks * 2 + ((lid >> 4) & 1));
                const uint32_t ra = swz(r, c16);
                LDM4(ah[i][0], ah[i][1], ah[i][2], ah[i][3], aHb + ra);
                LDM4(al[i][0], al[i][1], al[i][2], al[i][3], aLb + ra);
            }
            #pragma unroll
            for (int jp = 0; jp < 4; jp++) {
                uint32_t bh[2][2], bl[2][2];
                const uint32_t r = (uint32_t)(wn * 64 + jp * 16 + (lid & 7) +
                                              ((lid >> 4) & 1) * 8);
                const uint32_t c16 = (uint32_t)(ks * 2 + ((lid >> 3) & 1));
                const uint32_t rb = swz(r, c16);
                LDM4(bh[0][0], bh[0][1], bh[1][0], bh[1][1], bHb + rb);
                LDM4(bl[0][0], bl[0][1], bl[1][0], bl[1][1], bLb + rb);
                #pragma unroll
                for (int i = 0; i < 2; i++)
                    #pragma unroll
                    for (int jj = 0; jj < 2; jj++) {
                        float* a = acc[i][2 * jp + jj];
                        mma16816(a, ah[i], bh[jj]);   // hi*hi
                        mma16816(a, ah[i], bl[jj]);   // hi*lo
                        mma16816(a, al[i], bh[jj]);   // lo*hi
                    }
            }
        }
    }

    // ---------------- epilogue (register accumulators -> gmem) ----------------
    const int lr = lid >> 2, lc = (lid & 3) * 2;

    if (cfg == 1) {
        // fused unnormalized softmax: e = exp(s), split-bf16 P + row partials
        float rsum[2][2] = {{0.f, 0.f}, {0.f, 0.f}};
        #pragma unroll
        for (int i = 0; i < 2; i++) {
            #pragma unroll
            for (int j = 0; j < 8; j++) {
                const int gr0 = m0 + wm * 32 + i * 16 + lr;
                const int gc  = n0 + wn * 64 + j * 8 + lc;
                float e00 = __expf(acc[i][j][0]);
                float e01 = __expf(acc[i][j][1]);
                float e10 = __expf(acc[i][j][2]);
                float e11 = __expf(acc[i][j][3]);
                rsum[i][0] += e00 + e01;
                rsum[i][1] += e10 + e11;
                __nv_bfloat16 h0, l0, h1, l1;
                split2(e00, h0, l0); split2(e01, h1, l1);
                size_t o0 = ((size_t)bz * SEQ + gr0) * SEQ + gc;
                *(uint32_t*)&g_PH[o0] = pack2(h0, h1);
                *(uint32_t*)&g_PL[o0] = pack2(l0, l1);
                split2(e10, h0, l0); split2(e11, h1, l1);
                size_t o1 = ((size_t)bz * SEQ + gr0 + 8) * SEQ + gc;
                *(uint32_t*)&g_PH[o1] = pack2(h0, h1);
                *(uint32_t*)&g_PL[o1] = pack2(l0, l1);
            }
        }
        #pragma unroll
        for (int i = 0; i < 2; i++)
            #pragma unroll
            for (int h = 0; h < 2; h++) {
                float v = rsum[i][h];
                v += __shfl_xor_sync(0xFFFFFFFF, v, 1);
                v += __shfl_xor_sync(0xFFFFFFFF, v, 2);
                if ((lid & 3) == 0) {
                    const int grow = bz * SEQ + m0 + wm * 32 + i * 16 + lr + h * 8;
                    g_rowpart[(size_t)grow * 64 + nt * 2 + wn] = v;
                }
            }
        return;
    }

    #pragma unroll
    for (int i = 0; i < 2; i++) {
        #pragma unroll
        for (int j = 0; j < 8; j++) {
            const int gr0 = m0 + wm * 32 + i * 16 + lr;      // rows gr0, gr0+8
            const int gc  = n0 + wn * 64 + j * 8 + lc;       // cols gc, gc+1
            const float v00 = acc[i][j][0], v01 = acc[i][j][1];
            const float v10 = acc[i][j][2], v11 = acc[i][j][3];

            if (cfg == 3) {
                const float bb0 = b0[gc], bb1 = b0[gc + 1];
                *(float2*)&outp[(size_t)gr0 * DIM + gc] =
                    make_float2(v00 + bb0, v01 + bb1);
                *(float2*)&outp[(size_t)(gr0 + 8) * DIM + gc] =
                    make_float2(v10 + bb0, v11 + bb1);
            } else if (cfg == 2) {
                const float i0 = g_rsinv[bz * SEQ + gr0];
                const float i1 = g_rsinv[bz * SEQ + gr0 + 8];
                __nv_bfloat16 h0, l0, h1, l1;
                split2(v00 * i0, h0, l0); split2(v01 * i0, h1, l1);
                size_t o0 = ((size_t)bz * SEQ + gr0) * DIM + gc;
                *(uint32_t*)&g_YH[o0] = pack2(h0, h1);
                *(uint32_t*)&g_YL[o0] = pack2(l0, l1);
                split2(v10 * i1, h0, l0); split2(v11 * i1, h1, l1);
                size_t o1 = ((size_t)bz * SEQ + gr0 + 8) * DIM + gc;
                *(uint32_t*)&g_YH[o1] = pack2(h0, h1);
                *(uint32_t*)&g_YL[o1] = pack2(l0, l1);
            } else {  // cfg 0: QKV with bias, V transposed
                const int seg = gc >> 9, col = gc & 511;
                const float* bp = (seg == 0) ? b0 : (seg == 1) ? b1 : b2;
                const float bb0 = bp[col], bb1 = bp[col + 1];
                if (seg < 2) {
                    __nv_bfloat16* dH = (seg == 0) ? g_QH : g_KH;
                    __nv_bfloat16* dL = (seg == 0) ? g_QL : g_KL;
                    __nv_bfloat16 h0, l0, h1, l1;
                    split2(v00 + bb0, h0, l0); split2(v01 + bb1, h1, l1);
                    *(uint32_t*)&dH[(size_t)gr0 * DIM + col] = pack2(h0, h1);
                    *(uint32_t*)&dL[(size_t)gr0 * DIM + col] = pack2(l0, l1);
                    split2(v10 + bb0, h0, l0); split2(v11 + bb1, h1, l1);
                    *(uint32_t*)&dH[(size_t)(gr0 + 8) * DIM + col] = pack2(h0, h1);
                    *(uint32_t*)&dL[(size_t)(gr0 + 8) * DIM + col] = pack2(l0, l1);
                } else {
                    #pragma unroll
                    for (int e = 0; e < 4; e++) {
                        const int r = gr0 + (e >> 1) * 8;
                        const int c = col + (e & 1);
                        const float v = acc[i][j][e] + ((e & 1) ? bb1 : bb0);
                        __nv_bfloat16 h, l;
                        split2(v, h, l);
                        const int bbi = r >> 12, ss = r & 4095;
                        const size_t vi =
                            (size_t)bbi * DIM * SEQ + (size_t)c * SEQ + ss;
                        g_VtH[vi] = h;
                        g_VtL[vi] = l;
                    }
                }
            }
        }
    }
}

// ---------------------------------------------------------------------------
// Host launcher
// ---------------------------------------------------------------------------
extern "C" void kernel_launch(void* const* d_in, const int* in_sizes, int n_in,
                              void* d_out, int out_size) {
    (void)in_sizes; (void)n_in; (void)out_size;
    const float* x  = (const float*)d_in[0];
    const float* Wq = (const float*)d_in[1];
    const float* bq = (const float*)d_in[2];
    const float* Wk = (const float*)d_in[3];
    const float* bk = (const float*)d_in[4];
    const float* Wv = (const float*)d_in[5];
    const float* bv = (const float*)d_in[6];
    const float* Wo = (const float*)d_in[7];
    const float* bo = (const float*)d_in[8];
    float* out = (float*)d_out;

    cudaFuncSetAttribute(k_gemm, cudaFuncAttributeMaxDynamicSharedMemorySize, SMEMB);

    k_prep_x<<<(M0 * DIM + 255) / 256, 256>>>(x);
    k_prep_w<<<(4 * DIM * DIM + 255) / 256, 256>>>(Wq, Wk, Wv, Wo);

    // QKV: M=16384, N=1536
    k_gemm<<<dim3(12, 128, 1), 256, SMEMB>>>(0, bq, bk, bv, nullptr);
    // scores + fused exp/partial-sum epilogue: per batch M=N=4096
    k_gemm<<<dim3(32, 32, BATCH), 256, SMEMB>>>(1, nullptr, nullptr, nullptr, nullptr);
    // rowsum reduce -> 1/sum
    k_rowsum<<<(M0 + 255) / 256, 256>>>();
    // PV (normalization folded into epilogue): per batch M=4096, N=512, K=4096
    k_gemm<<<dim3(4, 32, BATCH), 256, SMEMB>>>(2, nullptr, nullptr, nullptr, nullptr);
    // out: M=16384, N=512
    k_gemm<<<dim3(4, 128, 1), 256, SMEMB>>>(3, bo, nullptr, nullptr, out);
}

// round 7
// speedup vs baseline: 1.4165x; 1.4165x over previous
#include <cuda_runtime.h>
#include <cuda_bf16.h>
#include <cstdint>

#define SEQ   4096
#define BATCH 4
#define DIM   512
#define M0    (BATCH * SEQ)

// ---------------------------------------------------------------------------
// Device scratch (allocation-free rule: __device__ globals)
// ---------------------------------------------------------------------------
__device__ __nv_bfloat16 g_XH[(size_t)M0 * DIM];
__device__ __nv_bfloat16 g_XL[(size_t)M0 * DIM];
__device__ __nv_bfloat16 g_WtH[4 * DIM * DIM];   // Wq^T,Wk^T,Wv^T,Wo^T (hi)
__device__ __nv_bfloat16 g_WtL[4 * DIM * DIM];   // (lo)
__device__ __nv_bfloat16 g_QH[(size_t)M0 * DIM];
__device__ __nv_bfloat16 g_QL[(size_t)M0 * DIM];
__device__ __nv_bfloat16 g_KH[(size_t)M0 * DIM];
__device__ __nv_bfloat16 g_KL[(size_t)M0 * DIM];
__device__ __nv_bfloat16 g_VtH[(size_t)BATCH * DIM * SEQ];  // [b][h][s]
__device__ __nv_bfloat16 g_VtL[(size_t)BATCH * DIM * SEQ];
__device__ __nv_bfloat16 g_PH[(size_t)BATCH * SEQ * SEQ];   // unnormalized exp(S)
__device__ __nv_bfloat16 g_PL[(size_t)BATCH * SEQ * SEQ];
__device__ float         g_rowpart[(size_t)M0 * 64];        // per-row partial sums
__device__ float         g_rsinv[M0];                       // 1/rowsum
__device__ __nv_bfloat16 g_YH[(size_t)M0 * DIM];
__device__ __nv_bfloat16 g_YL[(size_t)M0 * DIM];

// ---------------------------------------------------------------------------
// PTX helpers (sm_103 baseline only: ldmatrix + mma.sync + cp.async)
// ---------------------------------------------------------------------------
__device__ __forceinline__ uint32_t smem_to_u32(const void* p) {
    uint32_t a;
    asm("{ .reg .u64 t; cvta.to.shared.u64 t, %1; cvt.u32.u64 %0, t; }"
        : "=r"(a) : "l"(p));
    return a;
}

__device__ __forceinline__ void cp16(uint32_t s, const void* g) {
    asm volatile("cp.async.cg.shared.global [%0], [%1], 16;" :: "r"(s), "l"(g));
}
#define CP_COMMIT() asm volatile("cp.async.commit_group;" ::: "memory")
#define CP_WAIT(n)  asm volatile("cp.async.wait_group %0;" :: "n"(n) : "memory")

#define LDM4(r0, r1, r2, r3, addr) \
    asm volatile("ldmatrix.sync.aligned.m8n8.x4.shared.b16 {%0,%1,%2,%3}, [%4];" \
                 : "=r"(r0), "=r"(r1), "=r"(r2), "=r"(r3) : "r"(addr))

__device__ __forceinline__ void mma16816(float* c, const uint32_t* a,
                                         const uint32_t* b) {
    asm volatile(
        "mma.sync.aligned.m16n8k16.row.col.f32.bf16.bf16.f32 "
        "{%0,%1,%2,%3}, {%4,%5,%6,%7}, {%8,%9}, {%0,%1,%2,%3};"
        : "+f"(c[0]), "+f"(c[1]), "+f"(c[2]), "+f"(c[3])
        : "r"(a[0]), "r"(a[1]), "r"(a[2]), "r"(a[3]), "r"(b[0]), "r"(b[1]));
}

__device__ __forceinline__ void split2(float v, __nv_bfloat16& h, __nv_bfloat16& l) {
    h = __float2bfloat16(v);
    l = __float2bfloat16(v - __bfloat162float(h));
}

__device__ __forceinline__ uint32_t pack2(__nv_bfloat16 a, __nv_bfloat16 b) {
    __nv_bfloat162 t = __halves2bfloat162(a, b);
    return *(uint32_t*)&t;
}

// ---------------------------------------------------------------------------
// Prep kernels
// ---------------------------------------------------------------------------
__global__ void k_prep_x(const float* __restrict__ x) {
    size_t i = (size_t)blockIdx.x * 256 + threadIdx.x;
    if (i < (size_t)M0 * DIM) split2(x[i], g_XH[i], g_XL[i]);
}

__global__ void k_prep_w(const float* __restrict__ Wq, const float* __restrict__ Wk,
                         const float* __restrict__ Wv, const float* __restrict__ Wo) {
    int i = blockIdx.x * 256 + threadIdx.x;
    if (i >= 4 * DIM * DIM) return;
    int w = i >> 18, r = (i >> 9) & 511, c = i & 511;
    const float* src = (w == 0) ? Wq : (w == 1) ? Wk : (w == 2) ? Wv : Wo;
    split2(src[c * DIM + r], g_WtH[i], g_WtL[i]);   // Wt[r=out][c=in] = W[c][r]
}

// Reduce 64 partials per row -> 1/rowsum
__global__ void k_rowsum() {
    int r = blockIdx.x * 256 + threadIdx.x;
    if (r >= M0) return;
    const float4* p = (const float4*)(g_rowpart + (size_t)r * 64);
    float s = 0.f;
    #pragma unroll
    for (int i = 0; i < 16; i++) {
        float4 v = p[i];
        s += (v.x + v.y) + (v.z + v.w);
    }
    g_rsinv[r] = 1.f / s;
}

// ---------------------------------------------------------------------------
// Split-bf16 GEMM via mma.sync: D[m][n] = sum_k A[m][k] * B[n][k]
// Tile 128x128, BK=32, double-buffered cp.async (proven r5 layout ROWB=80),
// CTA = 128 threads, 4 warps in 2(M) x 2(N), warp tile 64x64. 2 CTAs/SM.
// cfg 0: QKV   epi: +bias, split (V transposed)
// cfg 1: score epi: exp(s), split -> P, per-row partial sums (fused softmax)
// cfg 2: PV    epi: * 1/rowsum, split -> Y
// cfg 3: out   epi: +bias, fp32 -> d_out
// ---------------------------------------------------------------------------
#define ROWB   80
#define TILEB  (128 * ROWB)          // 10240
#define STAGEB (4 * TILEB)           // 40960
#define SMEMB  (2 * STAGEB)          // 81920

__global__ void __launch_bounds__(128, 2)
k_gemm(int cfg, const float* __restrict__ b0, const float* __restrict__ b1,
       const float* __restrict__ b2, float* __restrict__ outp) {
    extern __shared__ char smem[];
    const int tid = threadIdx.x, wid = tid >> 5, lid = tid & 31;
    const int wm = wid & 1, wn = wid >> 1;           // warp grid 2(M) x 2(N)
    const int nt = blockIdx.x, mt = blockIdx.y, bz = blockIdx.z;

    const __nv_bfloat16 *AH, *AL, *BH, *BL;
    int lda, ldb, K;
    if (cfg == 0) {
        AH = g_XH; AL = g_XL; BH = g_WtH; BL = g_WtL;
        lda = DIM; ldb = DIM; K = DIM;
    } else if (cfg == 1) {
        size_t ao = (size_t)bz * SEQ * DIM;
        AH = g_QH + ao; AL = g_QL + ao; BH = g_KH + ao; BL = g_KL + ao;
        lda = DIM; ldb = DIM; K = DIM;
    } else if (cfg == 2) {
        size_t ao = (size_t)bz * SEQ * SEQ, vo = (size_t)bz * DIM * SEQ;
        AH = g_PH + ao; AL = g_PL + ao; BH = g_VtH + vo; BL = g_VtL + vo;
        lda = SEQ; ldb = SEQ; K = SEQ;
    } else {
        AH = g_YH; AL = g_YL;
        BH = g_WtH + 3 * DIM * DIM; BL = g_WtL + 3 * DIM * DIM;
        lda = DIM; ldb = DIM; K = DIM;
    }

    const int m0 = mt * 128, n0 = nt * 128;
    const uint32_t sb = smem_to_u32(smem);

    const __nv_bfloat16* tp[4];
    tp[0] = AH + (size_t)m0 * lda;
    tp[1] = AL + (size_t)m0 * lda;
    tp[2] = BH + (size_t)n0 * ldb;
    tp[3] = BL + (size_t)n0 * ldb;

    float acc[4][8][4];
    #pragma unroll
    for (int i = 0; i < 4; i++)
        #pragma unroll
        for (int j = 0; j < 8; j++)
            #pragma unroll
            for (int e = 0; e < 4; e++) acc[i][j][e] = 0.f;

    const int nst = K >> 5;

    auto load_stage = [&](int s) {
        const uint32_t base = sb + (uint32_t)(s & 1) * STAGEB;
        const int k0 = s << 5;
        #pragma unroll
        for (int t = tid; t < 2048; t += 128) {
            const int tl = t >> 9;
            const int idx = t & 511;
            const int r = idx >> 2, c = idx & 3;
            const int ld = (tl < 2) ? lda : ldb;
            cp16(base + (uint32_t)tl * TILEB + (uint32_t)(r * ROWB + c * 16),
                 tp[tl] + (size_t)r * ld + (k0 + c * 8));
        }
        CP_COMMIT();
    };

    load_stage(0);

    for (int s = 0; s < nst; s++) {
        if (s + 1 < nst) {
            load_stage(s + 1);
            CP_WAIT(1);
        } else {
            CP_WAIT(0);
        }
        __syncthreads();

        const uint32_t sbase = sb + (uint32_t)(s & 1) * STAGEB;
        const uint32_t aHb = sbase, aLb = sbase + TILEB;
        const uint32_t bHb = sbase + 2 * TILEB, bLb = sbase + 3 * TILEB;

        #pragma unroll
        for (int ks = 0; ks < 2; ks++) {
            uint32_t ah[4][4], al[4][4];
            #pragma unroll
            for (int i = 0; i < 4; i++) {
                const uint32_t ra =
                    (uint32_t)((wm * 64 + i * 16 + (lid & 15)) * ROWB) +
                    (uint32_t)(ks * 32 + ((lid >> 4) & 1) * 16);
                LDM4(ah[i][0], ah[i][1], ah[i][2], ah[i][3], aHb + ra);
                LDM4(al[i][0], al[i][1], al[i][2], al[i][3], aLb + ra);
            }
            #pragma unroll
            for (int jp = 0; jp < 4; jp++) {
                uint32_t bh[2][2], bl[2][2];
                const uint32_t rb =
                    (uint32_t)((wn * 64 + jp * 16 + (lid & 7) +
                                ((lid >> 4) & 1) * 8) * ROWB) +
                    (uint32_t)(ks * 32 + ((lid >> 3) & 1) * 16);
                LDM4(bh[0][0], bh[0][1], bh[1][0], bh[1][1], bHb + rb);
                LDM4(bl[0][0], bl[0][1], bl[1][0], bl[1][1], bLb + rb);
                #pragma unroll
                for (int i = 0; i < 4; i++)
                    #pragma unroll
                    for (int jj = 0; jj < 2; jj++) {
                        float* a = acc[i][2 * jp + jj];
                        mma16816(a, ah[i], bh[jj]);   // hi*hi
                        mma16816(a, ah[i], bl[jj]);   // hi*lo
                        mma16816(a, al[i], bh[jj]);   // lo*hi
                    }
            }
        }
        __syncthreads();
    }

    // ---------------- epilogue (register accumulators -> gmem) ----------------
    const int lr = lid >> 2, lc = (lid & 3) * 2;

    if (cfg == 1) {
        // fused unnormalized softmax: e = exp(s), split-bf16 P + row partials
        float rsum[4][2];
        #pragma unroll
        for (int i = 0; i < 4; i++) { rsum[i][0] = 0.f; rsum[i][1] = 0.f; }
        #pragma unroll
        for (int i = 0; i < 4; i++) {
            #pragma unroll
            for (int j = 0; j < 8; j++) {
                const int gr0 = m0 + wm * 64 + i * 16 + lr;
                const int gc  = n0 + wn * 64 + j * 8 + lc;
                float e00 = __expf(acc[i][j][0]);
                float e01 = __expf(acc[i][j][1]);
                float e10 = __expf(acc[i][j][2]);
                float e11 = __expf(acc[i][j][3]);
                rsum[i][0] += e00 + e01;
                rsum[i][1] += e10 + e11;
                __nv_bfloat16 h0, l0, h1, l1;
                split2(e00, h0, l0); split2(e01, h1, l1);
                size_t o0 = ((size_t)bz * SEQ + gr0) * SEQ + gc;
                *(uint32_t*)&g_PH[o0] = pack2(h0, h1);
                *(uint32_t*)&g_PL[o0] = pack2(l0, l1);
                split2(e10, h0, l0); split2(e11, h1, l1);
                size_t o1 = ((size_t)bz * SEQ + gr0 + 8) * SEQ + gc;
                *(uint32_t*)&g_PH[o1] = pack2(h0, h1);
                *(uint32_t*)&g_PL[o1] = pack2(l0, l1);
            }
        }
        #pragma unroll
        for (int i = 0; i < 4; i++)
            #pragma unroll
            for (int h = 0; h < 2; h++) {
                float v = rsum[i][h];
                v += __shfl_xor_sync(0xFFFFFFFF, v, 1);
                v += __shfl_xor_sync(0xFFFFFFFF, v, 2);
                if ((lid & 3) == 0) {
                    const int grow = bz * SEQ + m0 + wm * 64 + i * 16 + lr + h * 8;
                    g_rowpart[(size_t)grow * 64 + nt * 2 + wn] = v;
                }
            }
        return;
    }

    #pragma unroll
    for (int i = 0; i < 4; i++) {
        #pragma unroll
        for (int j = 0; j < 8; j++) {
            const int gr0 = m0 + wm * 64 + i * 16 + lr;      // rows gr0, gr0+8
            const int gc  = n0 + wn * 64 + j * 8 + lc;       // cols gc, gc+1
            const float v00 = acc[i][j][0], v01 = acc[i][j][1];
            const float v10 = acc[i][j][2], v11 = acc[i][j][3];

            if (cfg == 3) {
                const float bb0 = b0[gc], bb1 = b0[gc + 1];
                *(float2*)&outp[(size_t)gr0 * DIM + gc] =
                    make_float2(v00 + bb0, v01 + bb1);
                *(float2*)&outp[(size_t)(gr0 + 8) * DIM + gc] =
                    make_float2(v10 + bb0, v11 + bb1);
            } else if (cfg == 2) {
                const float i0 = g_rsinv[bz * SEQ + gr0];
                const float i1 = g_rsinv[bz * SEQ + gr0 + 8];
                __nv_bfloat16 h0, l0, h1, l1;
                split2(v00 * i0, h0, l0); split2(v01 * i0, h1, l1);
                size_t o0 = ((size_t)bz * SEQ + gr0) * DIM + gc;
                *(uint32_t*)&g_YH[o0] = pack2(h0, h1);
                *(uint32_t*)&g_YL[o0] = pack2(l0, l1);
                split2(v10 * i1, h0, l0); split2(v11 * i1, h1, l1);
                size_t o1 = ((size_t)bz * SEQ + gr0 + 8) * DIM + gc;
                *(uint32_t*)&g_YH[o1] = pack2(h0, h1);
                *(uint32_t*)&g_YL[o1] = pack2(l0, l1);
            } else {  // cfg 0: QKV with bias, V transposed
                const int seg = gc >> 9, col = gc & 511;
                const float* bp = (seg == 0) ? b0 : (seg == 1) ? b1 : b2;
                const float bb0 = bp[col], bb1 = bp[col + 1];
                if (seg < 2) {
                    __nv_bfloat16* dH = (seg == 0) ? g_QH : g_KH;
                    __nv_bfloat16* dL = (seg == 0) ? g_QL : g_KL;
                    __nv_bfloat16 h0, l0, h1, l1;
                    split2(v00 + bb0, h0, l0); split2(v01 + bb1, h1, l1);
                    *(uint32_t*)&dH[(size_t)gr0 * DIM + col] = pack2(h0, h1);
                    *(uint32_t*)&dL[(size_t)gr0 * DIM + col] = pack2(l0, l1);
                    split2(v10 + bb0, h0, l0); split2(v11 + bb1, h1, l1);
                    *(uint32_t*)&dH[(size_t)(gr0 + 8) * DIM + col] = pack2(h0, h1);
                    *(uint32_t*)&dL[(size_t)(gr0 + 8) * DIM + col] = pack2(l0, l1);
                } else {
                    #pragma unroll
                    for (int e = 0; e < 4; e++) {
                        const int r = gr0 + (e >> 1) * 8;
                        const int c = col + (e & 1);
                        const float v = acc[i][j][e] + ((e & 1) ? bb1 : bb0);
                        __nv_bfloat16 h, l;
                        split2(v, h, l);
                        const int bbi = r >> 12, ss = r & 4095;
                        const size_t vi =
                            (size_t)bbi * DIM * SEQ + (size_t)c * SEQ + ss;
                        g_VtH[vi] = h;
                        g_VtL[vi] = l;
                    }
                }
            }
        }
    }
}

// ---------------------------------------------------------------------------
// Host launcher
// ---------------------------------------------------------------------------
extern "C" void kernel_launch(void* const* d_in, const int* in_sizes, int n_in,
                              void* d_out, int out_size) {
    (void)in_sizes; (void)n_in; (void)out_size;
    const float* x  = (const float*)d_in[0];
    const float* Wq = (const float*)d_in[1];
    const float* bq = (const float*)d_in[2];
    const float* Wk = (const float*)d_in[3];
    const float* bk = (const float*)d_in[4];
    const float* Wv = (const float*)d_in[5];
    const float* bv = (const float*)d_in[6];
    const float* Wo = (const float*)d_in[7];
    const float* bo = (const float*)d_in[8];
    float* out = (float*)d_out;

    cudaFuncSetAttribute(k_gemm, cudaFuncAttributeMaxDynamicSharedMemorySize, SMEMB);

    k_prep_x<<<(M0 * DIM + 255) / 256, 256>>>(x);
    k_prep_w<<<(4 * DIM * DIM + 255) / 256, 256>>>(Wq, Wk, Wv, Wo);

    // QKV: M=16384, N=1536
    k_gemm<<<dim3(12, 128, 1), 128, SMEMB>>>(0, bq, bk, bv, nullptr);
    // scores + fused exp/partial-sum epilogue: per batch M=N=4096
    k_gemm<<<dim3(32, 32, BATCH), 128, SMEMB>>>(1, nullptr, nullptr, nullptr, nullptr);
    // rowsum reduce -> 1/sum
    k_rowsum<<<(M0 + 255) / 256, 256>>>();
    // PV (normalization folded into epilogue): per batch M=4096, N=512, K=4096
    k_gemm<<<dim3(4, 32, BATCH), 128, SMEMB>>>(2, nullptr, nullptr, nullptr, nullptr);
    // out: M=16384, N=512
    k_gemm<<<dim3(4, 128, 1), 128, SMEMB>>>(3, bo, nullptr, nullptr, out);
}